// round 9
// baseline (speedup 1.0000x reference)
#include <cuda_runtime.h>
#include <cuda_bf16.h>
#include <cstdint>

#define T_STEPS 28
#define HID 128
#define IND 28
#define NCLS 10
#define BATCH 8192
#define IG_GROUPS 4
#define IG_RPB (64 * IG_GROUPS)

typedef unsigned long long u64;

// 112 MB scratch: layer-0 input GEMM (+ fused biases), layout [t][b][c]
__device__ float g_xw0[T_STEPS * BATCH * HID];

// ---------------- packed fp32x2 helpers (input gemm) ----------------
#define FMA2(acc, a, b) \
    asm("fma.rn.f32x2 %0, %1, %2, %0;" : "+l"(acc) : "l"(a), "l"(b))
#define DUP2(d, s) \
    asm("mov.b64 %0, {%1, %1};" : "=l"(d) : "f"(s))
#define LDS2(a, b, addr) \
    asm("ld.shared.v2.u64 {%0, %1}, [%2];" : "=l"(a), "=l"(b) : "r"(addr))

__device__ __forceinline__ float ftanh(float x) {
    float e = __expf(2.0f * x);
    return 1.0f - __fdividef(2.0f, e + 1.0f);
}
__device__ __forceinline__ unsigned smaddr(const void* p) {
    return (unsigned)__cvta_generic_to_shared(p);
}

// ---------------- mma.sync helpers ----------------
__device__ __forceinline__ void ldsm4(uint32_t* r, uint32_t a) {
    asm volatile("ldmatrix.sync.aligned.m8n8.x4.shared.b16 {%0,%1,%2,%3}, [%4];"
                 : "=r"(r[0]), "=r"(r[1]), "=r"(r[2]), "=r"(r[3]) : "r"(a));
}
__device__ __forceinline__ void mma16816(float* d, const uint32_t* a,
                                         uint32_t b0, uint32_t b1) {
    asm volatile("mma.sync.aligned.m16n8k16.row.col.f32.bf16.bf16.f32 "
                 "{%0,%1,%2,%3}, {%4,%5,%6,%7}, {%8,%9}, {%0,%1,%2,%3};"
                 : "+f"(d[0]), "+f"(d[1]), "+f"(d[2]), "+f"(d[3])
                 : "r"(a[0]), "r"(a[1]), "r"(a[2]), "r"(a[3]), "r"(b0), "r"(b1));
}
__device__ __forceinline__ uint32_t pack2(float v0, float v1) {
    uint32_t r;
    asm("cvt.rn.bf16x2.f32 %0, %1, %2;" : "=r"(r) : "f"(v1), "f"(v0));
    return r;
}
__device__ __forceinline__ void cvt_pair(float v0, float v1,
                                         uint32_t& hi, uint32_t& lo) {
    uint32_t hp = pack2(v0, v1);
    float e0 = __uint_as_float(hp << 16);
    float e1 = __uint_as_float(hp & 0xffff0000u);
    hi = hp;
    lo = pack2(v0 - e0, v1 - e1);
}
#define STS32(a, v) asm volatile("st.shared.b32 [%0], %1;" :: "r"(a), "r"(v) : "memory")
#define BARG(id) asm volatile("bar.sync %0, %1;" :: "r"(id), "r"(64) : "memory")

// ---- weight tiles: [n][k] bf16, 128 rows x 256B, XOR-swizzled 16B chunks ----
#define WROWB 256
#define WTILE2 (128 * WROWB)          // 32768 B
#define SM_W   0                      // 6 tiles: W0h W0l W1h W1l W2h W2l
#define SM_HX  (6 * WTILE2)           // 196608: 4 group bufs x 8192 (hi@0, lo@4096)
#define SM_B1  (SM_HX + 4 * 8192)     // 229376: 128 f32
#define SMEM_TOTAL (SM_B1 + 512)      // 229888

__device__ __forceinline__ uint32_t wtile_off2(int n, int k) {
    return (uint32_t)n * WROWB + ((((uint32_t)k >> 3) ^ ((uint32_t)n & 7)) << 4)
           + ((uint32_t)k & 7) * 2;
}

// 3-term split-bf16 half-GEMM: d[8][4] += A(split) @ W_half(split)^T, K=128, N=64
__device__ __forceinline__ void gemm3h(float (*d)[4],
                                       const uint32_t (*ah)[4],
                                       const uint32_t (*al)[4],
                                       uint32_t baseHi, uint32_t baseLo,
                                       int kb, int xr) {
#pragma unroll
    for (int s = 0; s < 8; s++) {
        const uint32_t coff = (uint32_t)(((2 * s + kb) ^ xr) << 4);
#pragma unroll
        for (int j = 0; j < 4; j++) {
            uint32_t bh[4], bl[4];
            ldsm4(bh, baseHi + j * 4096 + coff);
            ldsm4(bl, baseLo + j * 4096 + coff);
            mma16816(d[2 * j],     ah[s], bh[0], bh[1]);
            mma16816(d[2 * j + 1], ah[s], bh[2], bh[3]);
            mma16816(d[2 * j],     ah[s], bl[0], bl[1]);
            mma16816(d[2 * j + 1], ah[s], bl[2], bl[3]);
            mma16816(d[2 * j],     al[s], bh[0], bh[1]);
            mma16816(d[2 * j + 1], al[s], bh[2], bh[3]);
        }
    }
}

__device__ __forceinline__ void ldA(uint32_t (*f)[4], uint32_t base, int kb, int xr) {
#pragma unroll
    for (int s = 0; s < 8; s++)
        ldsm4(f[s], base + (uint32_t)(((2 * s + kb) ^ xr) << 4));
}

// ---------------------------------------------------------------------------
// Kernel 1: xw0[t][b][:] = x[b,t,:] @ W_ih0^T + (b_ih0+b_hh0)
// Compute per 64-row group (rows = flattened (b,t)), stage result in smem,
// store coalesced 512B rows into the [t][b][c] layout.
// ---------------------------------------------------------------------------
__global__ __launch_bounds__(256, 1) void input_gemm_kernel(
    const float* __restrict__ x, const float* __restrict__ Wih0,
    const float* __restrict__ bih0, const float* __restrict__ bhh0)
{
    __shared__ float Wt[IND * HID];
    __shared__ float xsT[IND * 64];
    __shared__ float bs[HID];
    __shared__ float stage[64 * HID];   // 32 KB output tile

    const int tid = threadIdx.x;
    const int w = tid >> 5, lane = tid & 31;
    const int col0 = 16 * w, r0 = 2 * lane;

    for (int idx = tid; idx < HID * IND; idx += 256) {
        int j = idx / IND, d = idx - j * IND;
        Wt[d * HID + j] = Wih0[idx];
    }
    if (tid < HID) bs[tid] = bih0[tid] + bhh0[tid];
    __syncthreads();

    const unsigned aW = smaddr(Wt) + col0 * 4;
    const unsigned aB = smaddr(bs) + col0 * 4;
    const unsigned aS0 = smaddr(stage) + (r0 * HID + col0) * 4;

    for (int g = 0; g < IG_GROUPS; g++) {
        const int gr0 = blockIdx.x * IG_RPB + g * 64;
        __syncthreads();                       // xsT/stage free to overwrite
        for (int idx = tid; idx < 64 * IND; idx += 256) {
            int r = idx / IND, d = idx - r * IND;
            xsT[d * 64 + r] = x[gr0 * IND + idx];
        }
        __syncthreads();

        u64 acc0[8], acc1[8];
        LDS2(acc0[0], acc0[1], aB);
        LDS2(acc0[2], acc0[3], aB + 16);
        LDS2(acc0[4], acc0[5], aB + 32);
        LDS2(acc0[6], acc0[7], aB + 48);
#pragma unroll
        for (int j = 0; j < 8; j++) acc1[j] = acc0[j];

#pragma unroll
        for (int d = 0; d < IND; d++) {
            float2 hp = *(const float2*)&xsT[d * 64 + r0];
            u64 ha, hb; DUP2(ha, hp.x); DUP2(hb, hp.y);
            u64 w0, w1, w2, w3, w4, w5, w6, w7;
            LDS2(w0, w1, aW + d * 512);
            LDS2(w2, w3, aW + d * 512 + 16);
            LDS2(w4, w5, aW + d * 512 + 32);
            LDS2(w6, w7, aW + d * 512 + 48);
            FMA2(acc0[0], ha, w0); FMA2(acc0[1], ha, w1);
            FMA2(acc0[2], ha, w2); FMA2(acc0[3], ha, w3);
            FMA2(acc0[4], ha, w4); FMA2(acc0[5], ha, w5);
            FMA2(acc0[6], ha, w6); FMA2(acc0[7], ha, w7);
            FMA2(acc1[0], hb, w0); FMA2(acc1[1], hb, w1);
            FMA2(acc1[2], hb, w2); FMA2(acc1[3], hb, w3);
            FMA2(acc1[4], hb, w4); FMA2(acc1[5], hb, w5);
            FMA2(acc1[6], hb, w6); FMA2(acc1[7], hb, w7);
        }

        // stage into smem tile
        asm volatile("st.shared.v2.u64 [%0], {%1,%2};" :: "r"(aS0),       "l"(acc0[0]), "l"(acc0[1]) : "memory");
        asm volatile("st.shared.v2.u64 [%0], {%1,%2};" :: "r"(aS0 + 16),  "l"(acc0[2]), "l"(acc0[3]) : "memory");
        asm volatile("st.shared.v2.u64 [%0], {%1,%2};" :: "r"(aS0 + 32),  "l"(acc0[4]), "l"(acc0[5]) : "memory");
        asm volatile("st.shared.v2.u64 [%0], {%1,%2};" :: "r"(aS0 + 48),  "l"(acc0[6]), "l"(acc0[7]) : "memory");
        const unsigned aS1 = aS0 + HID * 4;
        asm volatile("st.shared.v2.u64 [%0], {%1,%2};" :: "r"(aS1),       "l"(acc1[0]), "l"(acc1[1]) : "memory");
        asm volatile("st.shared.v2.u64 [%0], {%1,%2};" :: "r"(aS1 + 16),  "l"(acc1[2]), "l"(acc1[3]) : "memory");
        asm volatile("st.shared.v2.u64 [%0], {%1,%2};" :: "r"(aS1 + 32),  "l"(acc1[4]), "l"(acc1[5]) : "memory");
        asm volatile("st.shared.v2.u64 [%0], {%1,%2};" :: "r"(aS1 + 48),  "l"(acc1[6]), "l"(acc1[7]) : "memory");
        __syncthreads();

        // coalesced store: each 128 consecutive threads write one row (512B)
        for (int i = tid; i < 64 * HID; i += 256) {
            int row = i >> 7, col = i & 127;
            int r = gr0 + row;
            int b = r / T_STEPS, t = r - b * T_STEPS;
            g_xw0[((size_t)t * BATCH + b) * HID + col] = stage[i];
        }
    }
}

// ---------------------------------------------------------------------------
// Kernel 2: mma.sync fused recurrence, N-split warp pairs, phase-staggered.
// ---------------------------------------------------------------------------
__global__ __launch_bounds__(256, 1) void rnn_mma_kernel(
    const float* __restrict__ Whh0, const float* __restrict__ Wih1,
    const float* __restrict__ Whh1, const float* __restrict__ bih1,
    const float* __restrict__ bhh1, const float* __restrict__ fcw,
    const float* __restrict__ fcb,  float* __restrict__ out)
{
    extern __shared__ char smem[];
    const int tid = threadIdx.x;
    const int wid = tid >> 5, lane = tid & 31;
    const int g = wid >> 1, u = wid & 1;

    // ---- prologue: split weights into bf16 hi/lo swizzled tiles ----
    {
        const float* srcs[3] = { Whh0, Wih1, Whh1 };
#pragma unroll
        for (int m = 0; m < 3; m++) {
            char* hiT = smem + SM_W + (2 * m) * WTILE2;
            char* loT = hiT + WTILE2;
            const float* src = srcs[m];
            for (int idx = tid; idx < HID * HID; idx += 256) {
                int n = idx >> 7, k = idx & 127;
                float wv = src[idx];
                __nv_bfloat16 h = __float2bfloat16(wv);
                float hf = __bfloat162float(h);
                __nv_bfloat16 l = __float2bfloat16(wv - hf);
                uint32_t off = wtile_off2(n, k);
                *(__nv_bfloat16*)(hiT + off) = h;
                *(__nv_bfloat16*)(loT + off) = l;
            }
        }
        float* b1s = (float*)(smem + SM_B1);
        if (tid < HID) b1s[tid] = bih1[tid] + bhh1[tid];
    }
    __syncthreads();

    // ---- phase stagger: decouple pairs sharing an SMSP ----
    if (g) {
        long long s0 = clock64();
        const long long dl = (long long)g * 1536;
        while (clock64() - s0 < dl) { }
    }

    const uint32_t sb = smaddr(smem);
    const int xr  = lane & 7;
    const int kbB = (lane >> 3) & 1;
    const int rowB = (lane & 7) + ((lane >> 4) << 3);
    const int kbA = (lane >> 4) & 1;
    const int rowA = (lane & 7) + (((lane >> 3) & 1) << 3);
    const int gr = lane >> 2, m2 = (lane & 3) * 2;

    const uint32_t wb0h = sb + 0 * WTILE2 + (uint32_t)(u * 64 + rowB) * WROWB;
    const uint32_t wb0l = sb + 1 * WTILE2 + (uint32_t)(u * 64 + rowB) * WROWB;
    const uint32_t wb1h = sb + 2 * WTILE2 + (uint32_t)(u * 64 + rowB) * WROWB;
    const uint32_t wb1l = sb + 3 * WTILE2 + (uint32_t)(u * 64 + rowB) * WROWB;
    const uint32_t wb2h = sb + 4 * WTILE2 + (uint32_t)(u * 64 + rowB) * WROWB;
    const uint32_t wb2l = sb + 5 * WTILE2 + (uint32_t)(u * 64 + rowB) * WROWB;

    const uint32_t hbuf = sb + SM_HX + (uint32_t)g * 8192;
    const uint32_t hAhi = hbuf + (uint32_t)rowA * WROWB;
    const uint32_t hAlo = hAhi + 4096;
    const uint32_t hw = hbuf + (uint32_t)gr * WROWB + (uint32_t)m2 * 2;

    const float* b1s = (const float*)(smem + SM_B1);
    const int barid = 1 + g;

    // xw0 [t][b][c]: this lane reads rows (rowbase+gr) and (+8)
    const int rowbase = blockIdx.x * 64 + g * 16;
    const size_t xstep = (size_t)BATCH * HID;
    const float* xb0 = g_xw0 + (size_t)(rowbase + gr) * HID;
    const float* xb8 = xb0 + (size_t)8 * HID;

    uint32_t a0h[8][4], a0l[8][4], a1h[8][4], a1l[8][4];
#pragma unroll
    for (int s = 0; s < 8; s++)
#pragma unroll
        for (int q = 0; q < 4; q++) { a0h[s][q] = 0; a0l[s][q] = 0; a1h[s][q] = 0; a1l[s][q] = 0; }

    float2 xpf[16];
#pragma unroll
    for (int nb = 0; nb < 8; nb++) {
        int cg = u * 64 + nb * 8 + m2;
        xpf[2 * nb]     = *(const float2*)(xb0 + cg);
        xpf[2 * nb + 1] = *(const float2*)(xb8 + cg);
    }

#pragma unroll 1
    for (int t = 0; t < T_STEPS; t++) {
        // ---------------- layer 0 ----------------
        float d0[8][4];
#pragma unroll
        for (int i = 0; i < 8; i++)
#pragma unroll
            for (int q = 0; q < 4; q++) d0[i][q] = 0.0f;

        if (t > 0) gemm3h(d0, a0h, a0l, wb0h, wb0l, kbB, xr);

        // epilogue 0: h0 = tanh(d0 + xw0_t) -> exchange (bf16 hi/lo)
#pragma unroll
        for (int nb = 0; nb < 8; nb++) {
            float v0 = ftanh(d0[nb][0] + xpf[2 * nb].x);
            float v1 = ftanh(d0[nb][1] + xpf[2 * nb].y);
            float v2 = ftanh(d0[nb][2] + xpf[2 * nb + 1].x);
            float v3 = ftanh(d0[nb][3] + xpf[2 * nb + 1].y);
            uint32_t hi0, lo0, hi8, lo8;
            cvt_pair(v0, v1, hi0, lo0);
            cvt_pair(v2, v3, hi8, lo8);
            uint32_t off = (uint32_t)(((u * 8 + nb) ^ gr) << 4);
            STS32(hw + off,        hi0);
            STS32(hw + off + 2048, hi8);
            STS32(hw + off + 4096, lo0);
            STS32(hw + off + 6144, lo8);
        }
        BARG(barid);
        ldA(a0h, hAhi, kbA, xr);
        ldA(a0l, hAlo, kbA, xr);
        BARG(barid);

        // prefetch next step's x (covered by layer-1 MMA latency)
        if (t + 1 < T_STEPS) {
            const float* x0n = xb0 + (size_t)(t + 1) * xstep;
            const float* x8n = xb8 + (size_t)(t + 1) * xstep;
#pragma unroll
            for (int nb = 0; nb < 8; nb++) {
                int cg = u * 64 + nb * 8 + m2;
                xpf[2 * nb]     = *(const float2*)(x0n + cg);
                xpf[2 * nb + 1] = *(const float2*)(x8n + cg);
            }
        }

        // ---------------- layer 1 ----------------
        float d1[8][4];
#pragma unroll
        for (int i = 0; i < 8; i++)
#pragma unroll
            for (int q = 0; q < 4; q++) d1[i][q] = 0.0f;

        gemm3h(d1, a0h, a0l, wb1h, wb1l, kbB, xr);
        if (t > 0) gemm3h(d1, a1h, a1l, wb2h, wb2l, kbB, xr);

        if (t + 1 < T_STEPS) {
#pragma unroll
            for (int nb = 0; nb < 8; nb++) {
                int cg = u * 64 + nb * 8 + m2;
                float2 bb = *(const float2*)(b1s + cg);
                float v0 = ftanh(d1[nb][0] + bb.x);
                float v1 = ftanh(d1[nb][1] + bb.y);
                float v2 = ftanh(d1[nb][2] + bb.x);
                float v3 = ftanh(d1[nb][3] + bb.y);
                uint32_t hi0, lo0, hi8, lo8;
                cvt_pair(v0, v1, hi0, lo0);
                cvt_pair(v2, v3, hi8, lo8);
                uint32_t off = (uint32_t)(((u * 8 + nb) ^ gr) << 4);
                STS32(hw + off,        hi0);
                STS32(hw + off + 2048, hi8);
                STS32(hw + off + 4096, lo0);
                STS32(hw + off + 6144, lo8);
            }
            BARG(barid);
            ldA(a1h, hAhi, kbA, xr);
            ldA(a1l, hAlo, kbA, xr);
            BARG(barid);
        } else {
            // ---------------- FC head ----------------
            __syncthreads();      // exchange buffers now free CTA-wide
            float* fstage  = (float*)(smem + SM_HX + 3 * 8192 + 2048);
            float* fbstage = (float*)(smem + SM_HX + 3 * 8192 + 7680);
            for (int i = tid; i < NCLS * HID; i += 256) fstage[i] = fcw[i];
            if (tid < NCLS) fbstage[tid] = fcb[tid];
            __syncthreads();

            float facc[2][NCLS];
#pragma unroll
            for (int r = 0; r < 2; r++)
#pragma unroll
                for (int cl = 0; cl < NCLS; cl++) facc[r][cl] = 0.0f;

#pragma unroll
            for (int nb = 0; nb < 8; nb++) {
                int cg = u * 64 + nb * 8 + m2;
                float2 bb = *(const float2*)(b1s + cg);
                float h0v = ftanh(d1[nb][0] + bb.x);
                float h1v = ftanh(d1[nb][1] + bb.y);
                float h8v = ftanh(d1[nb][2] + bb.x);
                float h9v = ftanh(d1[nb][3] + bb.y);
#pragma unroll
                for (int cl = 0; cl < NCLS; cl++) {
                    float2 fw = *(const float2*)(fstage + cl * HID + cg);
                    facc[0][cl] += h0v * fw.x + h1v * fw.y;
                    facc[1][cl] += h8v * fw.x + h9v * fw.y;
                }
            }
#pragma unroll
            for (int r = 0; r < 2; r++)
#pragma unroll
                for (int cl = 0; cl < NCLS; cl++) {
                    facc[r][cl] += __shfl_xor_sync(0xffffffff, facc[r][cl], 1);
                    facc[r][cl] += __shfl_xor_sync(0xffffffff, facc[r][cl], 2);
                }

            float* part = (float*)(smem + SM_HX + g * 8192);
            if ((lane & 3) == 0) {
#pragma unroll
                for (int cl = 0; cl < NCLS; cl++) {
                    part[(u * 16 + gr) * NCLS + cl]     = facc[0][cl];
                    part[(u * 16 + gr + 8) * NCLS + cl] = facc[1][cl];
                }
            }
            BARG(barid);
            if (u == 0 && lane < 16) {
                const int grow = rowbase + lane;
#pragma unroll
                for (int cl = 0; cl < NCLS; cl++)
                    out[(size_t)grow * NCLS + cl] =
                        part[lane * NCLS + cl] + part[(16 + lane) * NCLS + cl] + fbstage[cl];
            }
        }
    }
}

// ---------------------------------------------------------------------------
extern "C" void kernel_launch(void* const* d_in, const int* in_sizes, int n_in,
                              void* d_out, int out_size) {
    const float* x    = (const float*)d_in[0];
    const float* Wih0 = (const float*)d_in[1];
    const float* Whh0 = (const float*)d_in[2];
    const float* bih0 = (const float*)d_in[3];
    const float* bhh0 = (const float*)d_in[4];
    const float* Wih1 = (const float*)d_in[5];
    const float* Whh1 = (const float*)d_in[6];
    const float* bih1 = (const float*)d_in[7];
    const float* bhh1 = (const float*)d_in[8];
    const float* fcw  = (const float*)d_in[9];
    const float* fcb  = (const float*)d_in[10];
    float* out = (float*)d_out;

    cudaFuncSetAttribute(rnn_mma_kernel,
                         cudaFuncAttributeMaxDynamicSharedMemorySize, SMEM_TOTAL);

    input_gemm_kernel<<<(BATCH * T_STEPS) / IG_RPB, 256>>>(x, Wih0, bih0, bhh0);
    rnn_mma_kernel<<<BATCH / 64, 256, SMEM_TOTAL>>>(Whh0, Wih1, Whh1,
                                                    bih1, bhh1, fcw, fcb, out);
}